// round 15
// baseline (speedup 1.0000x reference)
#include <cuda_runtime.h>
#include <cuda_bf16.h>
#include <float.h>
#include <math.h>

// Problem constants
#define BATCH 8
#define NPTS  4096
#define KNN_K 16
#define TOTAL_PTS (BATCH * NPTS)   // 32768

// ---------------- scratch (static device memory; no allocation) ----------------
__device__ float    g_bufA[TOTAL_PTS * 128];   // 16 MB
__device__ float    g_bufB[TOTAL_PTS * 128];   // 16 MB
__device__ float    g_feat[TOTAL_PTS * 12];
__device__ int      g_idx[TOTAL_PTS * KNN_K];
__device__ float    g_kd_part[TOTAL_PTS * 2 * KNN_K];   // partial keys (acc space)
__device__ int      g_ki_part[TOTAL_PTS * 2 * KNN_K];   // partial indices
__device__ unsigned g_gmax[BATCH * 1024];
__device__ float    g_h[BATCH * 512];
// fused weights
__device__ float    g_fw1[128 * 64];           // c1w @ l1w
__device__ float    g_fb1[128];                // c1w @ l1b + c1b
__device__ float    g_fw2[1024 * 128];         // c2w @ l2w
__device__ float    g_fb2[1024];               // c2w @ l2b + c2b

// ---------------- float <-> ordered-uint encoding for atomicMax ----------------
__device__ __forceinline__ unsigned fenc(float f) {
    unsigned u = __float_as_uint(f);
    return (u & 0x80000000u) ? ~u : (u | 0x80000000u);
}
__device__ __forceinline__ float fdec(unsigned u) {
    unsigned v = (u & 0x80000000u) ? (u & 0x7fffffffu) : ~u;
    return __uint_as_float(v);
}

// ---------------- weight-fusion precompute kernels ------------------------------
__global__ void fuse1_kernel(const float* __restrict__ c1w, const float* __restrict__ l1w,
                             const float* __restrict__ l1b, const float* __restrict__ c1b) {
    __shared__ float sl[64 * 64];
    int tid = threadIdx.x;
    for (int t = tid; t < 4096; t += 256) sl[t] = l1w[t];
    __syncthreads();
    for (int t = tid; t < 128 * 64; t += 256) {
        int o = t >> 6, i = t & 63;
        float s = 0.f;
#pragma unroll 8
        for (int j = 0; j < 64; j++) s = fmaf(c1w[o * 64 + j], sl[j * 64 + i], s);
        g_fw1[t] = s;
    }
    if (tid < 128) {
        float s = c1b[tid];
#pragma unroll 8
        for (int j = 0; j < 64; j++) s = fmaf(c1w[tid * 64 + j], l1b[j], s);
        g_fb1[tid] = s;
    }
}

// fw2[o][i] = sum_j c2w[o][j] * l2w[j][i]; 128 blocks x 8 rows
__global__ __launch_bounds__(256) void fuse2_kernel(const float* __restrict__ c2w,
                                                    const float* __restrict__ l2w) {
    extern __shared__ float sl[];                 // 128*128
    const int tid = threadIdx.x;
    for (int t = tid; t < 16384; t += 256) sl[t] = l2w[t];
    __syncthreads();
    const int i  = tid & 127;
    const int og = tid >> 7;                      // 0..1
    const int o0 = blockIdx.x * 8 + og * 4;
    float s0 = 0.f, s1 = 0.f, s2 = 0.f, s3 = 0.f;
    const float* w0 = c2w + (size_t)(o0 + 0) * 128;
    const float* w1 = c2w + (size_t)(o0 + 1) * 128;
    const float* w2 = c2w + (size_t)(o0 + 2) * 128;
    const float* w3 = c2w + (size_t)(o0 + 3) * 128;
#pragma unroll 4
    for (int j = 0; j < 128; j++) {
        float xv = sl[j * 128 + i];
        s0 = fmaf(w0[j], xv, s0);
        s1 = fmaf(w1[j], xv, s1);
        s2 = fmaf(w2[j], xv, s2);
        s3 = fmaf(w3[j], xv, s3);
    }
    g_fw2[(size_t)(o0 + 0) * 128 + i] = s0;
    g_fw2[(size_t)(o0 + 1) * 128 + i] = s1;
    g_fw2[(size_t)(o0 + 2) * 128 + i] = s2;
    g_fw2[(size_t)(o0 + 3) * 128 + i] = s3;
}

__global__ void fuse2b_kernel(const float* __restrict__ c2w, const float* __restrict__ l2b,
                              const float* __restrict__ c2b) {
    int o = blockIdx.x * 256 + threadIdx.x;
    if (o < 1024) {
        float s = c2b[o];
#pragma unroll 8
        for (int j = 0; j < 128; j++) s = fmaf(c2w[o * 128 + j], l2b[j], s);
        g_fb2[o] = s;
    }
}

// ---------------- KNN part 1: Q=2 packed-pair scan, per-half partial top-16 ------
// Each THREAD owns 2 queries (n, n+128); tile LDS + loop overhead amortized over
// both. Keys in acc space: d = dot(pn,pm) - 0.5*||pm||^2. Candidate pairs via
// fma.rn.f32x2. grid (128, 2): x = 256-query tile (128 threads x 2), y = half.
__global__ __launch_bounds__(128) void knn_part_kernel(const float* __restrict__ pts) {
    const int b  = blockIdx.x >> 4;
    const int n0 = ((blockIdx.x & 15) << 8) + threadIdx.x;   // query A
    const int n1 = n0 + 128;                                  // query B
    const int m0 = blockIdx.y * 2048;
    const float* px = pts + b * 3 * NPTS;

    const float xa = px[n0], ya = px[NPTS + n0], za = px[2 * NPTS + n0];
    const float xb = px[n1], yb = px[NPTS + n1], zb = px[2 * NPTS + n1];
    unsigned long long xa2, ya2, za2, xb2, yb2, zb2;
    asm("mov.b64 %0, {%1, %1};" : "=l"(xa2) : "f"(xa));
    asm("mov.b64 %0, {%1, %1};" : "=l"(ya2) : "f"(ya));
    asm("mov.b64 %0, {%1, %1};" : "=l"(za2) : "f"(za));
    asm("mov.b64 %0, {%1, %1};" : "=l"(xb2) : "f"(xb));
    asm("mov.b64 %0, {%1, %1};" : "=l"(yb2) : "f"(yb));
    asm("mov.b64 %0, {%1, %1};" : "=l"(zb2) : "f"(zb));

    float kdA[16]; int kiA[16];
    float kdB[16]; int kiB[16];
#pragma unroll
    for (int j = 0; j < 16; j++) {
        kdA[j] = -FLT_MAX; kiA[j] = 0;
        kdB[j] = -FLT_MAX; kiB[j] = 0;
    }

    __shared__ ulonglong2 tile_xy[1024];   // 16 KB: (x0,x1 | y0,y1)
    __shared__ ulonglong2 tile_zw[1024];   // 16 KB: (z0,z1 | w0,w1), w=-0.5*||p||^2

    for (int t = threadIdx.x; t < 1024; t += 128) {
        int m = m0 + 2 * t;
        float x0 = px[m],            x1 = px[m + 1];
        float y0 = px[NPTS + m],     y1 = px[NPTS + m + 1];
        float z0 = px[2 * NPTS + m], z1 = px[2 * NPTS + m + 1];
        float w0 = -0.5f * fmaf(x0, x0, fmaf(y0, y0, z0 * z0));
        float w1 = -0.5f * fmaf(x1, x1, fmaf(y1, y1, z1 * z1));
        *(float4*)&tile_xy[t] = make_float4(x0, x1, y0, y1);
        *(float4*)&tile_zw[t] = make_float4(z0, z1, w0, w1);
    }
    __syncthreads();

#pragma unroll 2
    for (int t = 0; t < 1024; t++) {
        ulonglong2 xy = tile_xy[t];   // .x = x01, .y = y01
        ulonglong2 zw = tile_zw[t];   // .x = z01, .y = w01
        unsigned long long dA, dB;
        asm("fma.rn.f32x2 %0, %1, %2, %3;" : "=l"(dA) : "l"(xa2), "l"(xy.x), "l"(zw.y));
        asm("fma.rn.f32x2 %0, %1, %2, %3;" : "=l"(dB) : "l"(xb2), "l"(xy.x), "l"(zw.y));
        asm("fma.rn.f32x2 %0, %1, %2, %3;" : "=l"(dA) : "l"(ya2), "l"(xy.y), "l"(dA));
        asm("fma.rn.f32x2 %0, %1, %2, %3;" : "=l"(dB) : "l"(yb2), "l"(xy.y), "l"(dB));
        asm("fma.rn.f32x2 %0, %1, %2, %3;" : "=l"(dA) : "l"(za2), "l"(zw.x), "l"(dA));
        asm("fma.rn.f32x2 %0, %1, %2, %3;" : "=l"(dB) : "l"(zb2), "l"(zw.x), "l"(dB));
        float a0, a1, b0, b1;
        asm("mov.b64 {%0, %1}, %2;" : "=f"(a0), "=f"(a1) : "l"(dA));
        asm("mov.b64 {%0, %1}, %2;" : "=f"(b0), "=f"(b1) : "l"(dB));

        if (fmaxf(a0, a1) > kdA[15]) {
#pragma unroll 1
            for (int h = 0; h < 2; h++) {
                float d = (h == 0) ? a0 : a1;
                if (d > kdA[15]) {
                    const int ci = m0 + 2 * t + h;
                    bool done = false;
#pragma unroll
                    for (int j = 15; j > 0; --j) {
                        if (!done) {
                            if (kdA[j - 1] < d) {
                                kdA[j] = kdA[j - 1]; kiA[j] = kiA[j - 1];
                                if (j == 1) { kdA[0] = d; kiA[0] = ci; }
                            } else {
                                kdA[j] = d; kiA[j] = ci;
                                done = true;
                            }
                        }
                    }
                }
            }
        }
        if (fmaxf(b0, b1) > kdB[15]) {
#pragma unroll 1
            for (int h = 0; h < 2; h++) {
                float d = (h == 0) ? b0 : b1;
                if (d > kdB[15]) {
                    const int ci = m0 + 2 * t + h;
                    bool done = false;
#pragma unroll
                    for (int j = 15; j > 0; --j) {
                        if (!done) {
                            if (kdB[j - 1] < d) {
                                kdB[j] = kdB[j - 1]; kiB[j] = kiB[j - 1];
                                if (j == 1) { kdB[0] = d; kiB[0] = ci; }
                            } else {
                                kdB[j] = d; kiB[j] = ci;
                                done = true;
                            }
                        }
                    }
                }
            }
        }
    }

    const int pA = b * NPTS + n0;
    const int pB = b * NPTS + n1;
    float* odA = g_kd_part + ((size_t)pA * 2 + blockIdx.y) * KNN_K;
    int*   oiA = g_ki_part + ((size_t)pA * 2 + blockIdx.y) * KNN_K;
    float* odB = g_kd_part + ((size_t)pB * 2 + blockIdx.y) * KNN_K;
    int*   oiB = g_ki_part + ((size_t)pB * 2 + blockIdx.y) * KNN_K;
#pragma unroll
    for (int j = 0; j < 16; j++) {
        odA[j] = kdA[j]; oiA[j] = kiA[j];
        odB[j] = kdB[j]; oiB[j] = kiB[j];
    }
}

// ---------------- KNN part 2: merge the two sorted halves -----------------------
// Half 0 indices (0..2047) all < half 1 (2048..4095): ties -> half 0 = lower index,
// matching lax.top_k stable tie-breaking.
__global__ void knn_merge_kernel() {
    int p = blockIdx.x * 256 + threadIdx.x;
    if (p >= TOTAL_PTS) return;
    const float* dA = g_kd_part + (size_t)p * 2 * KNN_K;
    const int*   iA = g_ki_part + (size_t)p * 2 * KNN_K;
    const float* dB = dA + KNN_K;
    const int*   iB = iA + KNN_K;
    int* op = g_idx + (size_t)p * KNN_K;
    int a = 0, c = 0;
#pragma unroll
    for (int j = 0; j < 16; j++) {
        bool takeA = (c >= 16) || (a < 16 && dA[a] >= dB[c]);
        op[j] = takeA ? iA[a] : iB[c];
        if (takeA) a++; else c++;
    }
}

// ---------------- local covariance features: [p][12] --------------------------
__global__ void feat_kernel(const float* __restrict__ pts) {
    int p = blockIdx.x * 256 + threadIdx.x;
    if (p >= TOTAL_PTS) return;
    int b = p >> 12, n = p & (NPTS - 1);
    const float* px = pts + b * 3 * NPTS;
    int i0 = g_idx[p * KNN_K + 0];
    int i1 = g_idx[p * KNN_K + 1];
    float a0 = px[i0], a1 = px[NPTS + i0], a2 = px[2 * NPTS + i0];
    float c0 = px[i1], c1 = px[NPTS + i1], c2 = px[2 * NPTS + i1];
    float* f = g_feat + p * 12;
    f[0] = px[n]; f[1] = px[NPTS + n]; f[2] = px[2 * NPTS + n];
    f[3] = a0 * c0; f[4]  = a0 * c1; f[5]  = a0 * c2;
    f[6] = a1 * c0; f[7]  = a1 * c1; f[8]  = a1 * c2;
    f[9] = a2 * c0; f[10] = a2 * c1; f[11] = a2 * c2;
}

// ---------------- pointwise dense layer (oc-split, 256 pts/block) ----------------
template <int DIN, int DOUTB, int DOUT, bool RELU>
__global__ __launch_bounds__(256) void dense_kernel(
    const float* __restrict__ in, const float* __restrict__ W,
    const float* __restrict__ bias, float* __restrict__ out) {
    constexpr int SW = DOUTB + 4;
    extern __shared__ float sm[];
    float* sW  = sm;                            // DIN * SW   (sW[i][oc])
    float* sB  = sW + DIN * SW;                 // DOUTB
    float* sIn = sB + DOUTB;                    // 256 * (DIN+1)
    const int tid = threadIdx.x;
    const int oc0 = blockIdx.y * DOUTB;

    for (int t = tid; t < DIN * DOUTB; t += 256) {
        int oc = t / DIN, i = t - oc * DIN;
        sW[i * SW + oc] = W[(size_t)oc0 * DIN + t];
    }
    for (int t = tid; t < DOUTB; t += 256) sB[t] = bias[oc0 + t];
    const int p0 = blockIdx.x * 256;
    for (int t = tid; t < 256 * DIN; t += 256) {
        int r = t / DIN, c = t - r * DIN;
        sIn[r * (DIN + 1) + c] = in[(size_t)(p0 + r) * DIN + c];
    }
    __syncthreads();

    const float* myin = sIn + tid * (DIN + 1);
    float* op = out + (size_t)(p0 + tid) * DOUT + oc0;

#pragma unroll
    for (int c0 = 0; c0 < DOUTB; c0 += 16) {
        float acc[16];
#pragma unroll
        for (int j = 0; j < 16; j++) acc[j] = sB[c0 + j];
#pragma unroll 4
        for (int i = 0; i < DIN; i++) {
            float xi = myin[i];
            const float4* wr = (const float4*)(sW + i * SW + c0);
#pragma unroll
            for (int q = 0; q < 4; q++) {
                float4 w4 = wr[q];
                acc[q * 4 + 0] = fmaf(w4.x, xi, acc[q * 4 + 0]);
                acc[q * 4 + 1] = fmaf(w4.y, xi, acc[q * 4 + 1]);
                acc[q * 4 + 2] = fmaf(w4.z, xi, acc[q * 4 + 2]);
                acc[q * 4 + 3] = fmaf(w4.w, xi, acc[q * 4 + 3]);
            }
        }
#pragma unroll
        for (int q = 0; q < 4; q++) {
            float4 v;
            v.x = acc[q * 4 + 0]; v.y = acc[q * 4 + 1];
            v.z = acc[q * 4 + 2]; v.w = acc[q * 4 + 3];
            if (RELU) {
                v.x = fmaxf(v.x, 0.f); v.y = fmaxf(v.y, 0.f);
                v.z = fmaxf(v.z, 0.f); v.w = fmaxf(v.w, 0.f);
            }
            ((float4*)(op + c0))[q] = v;
        }
    }
}

// ---------------- neighbor max-pool over idx (float4 vectorized) -----------------
template <int D>
__global__ void maxpool_kernel(const float* __restrict__ in, float* __restrict__ out) {
    constexpr int DV = D / 4;
    int t = blockIdx.x * 256 + threadIdx.x;
    if (t >= TOTAL_PTS * DV) return;
    int p = t / DV;
    int c4 = t - p * DV;
    int base = (p >> 12) << 12;
    const int* id = g_idx + p * KNN_K;
    float4 m = make_float4(-FLT_MAX, -FLT_MAX, -FLT_MAX, -FLT_MAX);
#pragma unroll
    for (int k = 0; k < KNN_K; k++) {
        int j = id[k];
        float4 v = *(const float4*)(in + (size_t)(base + j) * D + c4 * 4);
        m.x = fmaxf(m.x, v.x); m.y = fmaxf(m.y, v.y);
        m.z = fmaxf(m.z, v.z); m.w = fmaxf(m.w, v.w);
    }
    ((float4*)out)[t] = m;
}

// ---------------- reset gmax -----------------------------------------------------
__global__ void reset_kernel() {
    int t = blockIdx.x * 256 + threadIdx.x;
    if (t < BATCH * 1024) g_gmax[t] = 0u;
}

// ---------------- fused l2+c2 (128->1024) GEMM + global max ----------------------
__global__ __launch_bounds__(256) void c2max_kernel(const float* __restrict__ y) {
    extern __shared__ float sm[];
    float* sW = sm;                 // [i64][oc128] stride 132
    float* sX = sW + 64 * 132;      // [i64][p128]  stride 132
    float* sB = sX + 64 * 132;      // 128
    const int tid = threadIdx.x;
    const int pt0 = blockIdx.x * 128;
    const int oc0 = blockIdx.y * 128;
    const int b = pt0 >> 12;
    const int tx4 = (tid & 15) * 4, ty4 = (tid >> 4) * 4;

    if (tid < 128) sB[tid] = g_fb2[oc0 + tid];

    float acc[8][8];
#pragma unroll
    for (int j = 0; j < 8; j++)
#pragma unroll
        for (int k = 0; k < 8; k++) acc[j][k] = 0.f;

    for (int kc = 0; kc < 128; kc += 64) {
        __syncthreads();
        for (int t = tid; t < 8192; t += 256) {
            int r = t >> 6, i = t & 63;
            sW[i * 132 + r] = g_fw2[(size_t)(oc0 + r) * 128 + kc + i];
            sX[i * 132 + r] = y[(size_t)(pt0 + r) * 128 + kc + i];
        }
        __syncthreads();

#pragma unroll 2
        for (int i = 0; i < 64; i++) {
            const float* wr = sW + i * 132;
            const float* xr = sX + i * 132;
            float4 w0 = *(const float4*)(wr + ty4);
            float4 w1 = *(const float4*)(wr + 64 + ty4);
            float4 x0 = *(const float4*)(xr + tx4);
            float4 x1 = *(const float4*)(xr + 64 + tx4);
            float wv[8] = {w0.x, w0.y, w0.z, w0.w, w1.x, w1.y, w1.z, w1.w};
            float xv[8] = {x0.x, x0.y, x0.z, x0.w, x1.x, x1.y, x1.z, x1.w};
#pragma unroll
            for (int j = 0; j < 8; j++)
#pragma unroll
                for (int k = 0; k < 8; k++)
                    acc[j][k] = fmaf(wv[j], xv[k], acc[j][k]);
        }
    }

#pragma unroll
    for (int j = 0; j < 8; j++) {
        int ocl = (j < 4) ? (ty4 + j) : (64 + ty4 + j - 4);
        float m = acc[j][0];
#pragma unroll
        for (int k = 1; k < 8; k++) m = fmaxf(m, acc[j][k]);
        m += sB[ocl];
#pragma unroll
        for (int off = 8; off >= 1; off >>= 1)
            m = fmaxf(m, __shfl_xor_sync(0xffffffffu, m, off));
        if ((tid & 15) == 0)
            atomicMax(&g_gmax[b * 1024 + oc0 + ocl], fenc(m));
    }
}

// ---------------- mlp2 -----------------------------------------------------------
// grid (BATCH, 4): each block computes 128 outputs, K split x2 per output pair.
__global__ __launch_bounds__(256) void mlp2a_kernel(const float* __restrict__ w,
                                                    const float* __restrict__ bias) {
    int b = blockIdx.x;
    __shared__ float sg[1024];
    for (int t = threadIdx.x; t < 1024; t += 256) sg[t] = fdec(g_gmax[b * 1024 + t]);
    __syncthreads();
    int o  = blockIdx.y * 128 + (threadIdx.x >> 1);
    int kh = (threadIdx.x & 1) * 512;
    const float* wr = w + (size_t)o * 1024 + kh;
    const float* xr = sg + kh;
    float acc = 0.f;
#pragma unroll 8
    for (int i = 0; i < 512; i++) acc = fmaf(wr[i], xr[i], acc);
    acc += __shfl_xor_sync(0xffffffffu, acc, 1);
    if ((threadIdx.x & 1) == 0)
        g_h[b * 512 + o] = fmaxf(acc + bias[o], 0.f);
}

__global__ void mlp2b_kernel(const float* __restrict__ w, const float* __restrict__ bias,
                             float* __restrict__ out) {
    int b = blockIdx.x;
    __shared__ float sh[512];
    if (threadIdx.x < 512) sh[threadIdx.x] = g_h[b * 512 + threadIdx.x];
    __syncthreads();
    int o = threadIdx.x;
    if (o < 512) {
        float acc = bias[o];
        const float* wr = w + (size_t)o * 512;
#pragma unroll 8
        for (int i = 0; i < 512; i++) acc = fmaf(wr[i], sh[i], acc);
        out[b * 512 + o] = acc;
    }
}

// ---------------- launch ---------------------------------------------------------
extern "C" void kernel_launch(void* const* d_in, const int* in_sizes, int n_in,
                              void* d_out, int out_size) {
    const float* pts  = (const float*)d_in[0];
    const float* m1w1 = (const float*)d_in[1];  const float* m1b1 = (const float*)d_in[2];
    const float* m1w2 = (const float*)d_in[3];  const float* m1b2 = (const float*)d_in[4];
    const float* m1w3 = (const float*)d_in[5];  const float* m1b3 = (const float*)d_in[6];
    const float* l1w  = (const float*)d_in[7];  const float* l1b  = (const float*)d_in[8];
    const float* c1w  = (const float*)d_in[9];  const float* c1b  = (const float*)d_in[10];
    const float* l2w  = (const float*)d_in[11]; const float* l2b  = (const float*)d_in[12];
    const float* c2w  = (const float*)d_in[13]; const float* c2b  = (const float*)d_in[14];
    const float* m2w1 = (const float*)d_in[15]; const float* m2b1 = (const float*)d_in[16];
    const float* m2w2 = (const float*)d_in[17]; const float* m2b2 = (const float*)d_in[18];
    float* out = (float*)d_out;

    float *bufA = nullptr, *bufB = nullptr, *feat = nullptr, *fw1 = nullptr, *fb1 = nullptr;
    cudaGetSymbolAddress((void**)&bufA, g_bufA);
    cudaGetSymbolAddress((void**)&bufB, g_bufB);
    cudaGetSymbolAddress((void**)&feat, g_feat);
    cudaGetSymbolAddress((void**)&fw1,  g_fw1);
    cudaGetSymbolAddress((void**)&fb1,  g_fb1);

    // dynamic smem sizes (floats * 4)
    const int smem_d12  = (12 * 36 + 32 + 256 * 13) * 4;    // ~15.2 KB
    const int smem_d64  = (64 * 36 + 32 + 256 * 65) * 4;    // ~75.9 KB
    const int smem_c2   = (2 * 64 * 132 + 128) * 4;         // ~68.1 KB
    const int smem_f2   = 128 * 128 * 4;                    // 64 KB

    cudaFuncSetAttribute(dense_kernel<64, 32, 64, true>,
                         cudaFuncAttributeMaxDynamicSharedMemorySize, smem_d64);
    cudaFuncSetAttribute(dense_kernel<64, 32, 128, true>,
                         cudaFuncAttributeMaxDynamicSharedMemorySize, smem_d64);
    cudaFuncSetAttribute(c2max_kernel,
                         cudaFuncAttributeMaxDynamicSharedMemorySize, smem_c2);
    cudaFuncSetAttribute(fuse2_kernel,
                         cudaFuncAttributeMaxDynamicSharedMemorySize, smem_f2);

    // 1. fused-weight precompute (independent of knn)
    fuse1_kernel<<<1, 256>>>(c1w, l1w, l1b, c1b);
    fuse2_kernel<<<128, 256, smem_f2>>>(c2w, l2w);
    fuse2b_kernel<<<4, 256>>>(c2w, l2b, c2b);
    // 2. KNN (Q=2 f32x2 packed-pair scan, split candidate halves) + merge + feats
    {
        dim3 g(128, 2);
        knn_part_kernel<<<g, 128>>>(pts);
    }
    knn_merge_kernel<<<128, 256>>>();
    feat_kernel<<<128, 256>>>(pts);
    // 3. mlp1
    {
        dim3 g(TOTAL_PTS / 256, 2);
        dense_kernel<12, 32, 64, true><<<g, 256, smem_d12>>>(feat, m1w1, m1b1, bufA);
        dense_kernel<64, 32, 64, true><<<g, 256, smem_d64>>>(bufA, m1w2, m1b2, bufB);
        dense_kernel<64, 32, 64, true><<<g, 256, smem_d64>>>(bufB, m1w3, m1b3, bufA);
    }
    // 4. graph layer (l1+c1 fused)
    maxpool_kernel<64><<<TOTAL_PTS * 16 / 256, 256>>>(bufA, bufB);
    {
        dim3 g(TOTAL_PTS / 256, 4);
        dense_kernel<64, 32, 128, true><<<g, 256, smem_d64>>>(bufB, fw1, fb1, bufA);
    }
    maxpool_kernel<128><<<TOTAL_PTS * 32 / 256, 256>>>(bufA, bufB);
    // 5. fused l2+c2 + global max
    reset_kernel<<<32, 256>>>();
    {
        dim3 grid(TOTAL_PTS / 128, 8);
        c2max_kernel<<<grid, 256, smem_c2>>>(bufB);
    }
    // 6. mlp2
    {
        dim3 g(BATCH, 4);
        mlp2a_kernel<<<g, 256>>>(m2w1, m2b1);
    }
    mlp2b_kernel<<<BATCH, 512>>>(m2w2, m2b2, out);
}

// round 16
// speedup vs baseline: 1.1063x; 1.1063x over previous
#include <cuda_runtime.h>
#include <cuda_bf16.h>
#include <float.h>
#include <math.h>

// Problem constants
#define BATCH 8
#define NPTS  4096
#define KNN_K 16
#define TOTAL_PTS (BATCH * NPTS)   // 32768

// ---------------- scratch (static device memory; no allocation) ----------------
__device__ float    g_bufA[TOTAL_PTS * 128];   // 16 MB
__device__ float    g_bufB[TOTAL_PTS * 128];   // 16 MB
__device__ float    g_feat[TOTAL_PTS * 12];
__device__ int      g_idx[TOTAL_PTS * KNN_K];
__device__ float    g_kd_part[TOTAL_PTS * 2 * KNN_K];   // partial keys (acc space)
__device__ int      g_ki_part[TOTAL_PTS * 2 * KNN_K];   // partial indices
__device__ unsigned g_gmax[BATCH * 1024];
__device__ float    g_h[BATCH * 512];
// fused weights
__device__ float    g_fw1[128 * 64];           // c1w @ l1w
__device__ float    g_fb1[128];                // c1w @ l1b + c1b
__device__ float    g_fw2[1024 * 128];         // c2w @ l2w
__device__ float    g_fb2[1024];               // c2w @ l2b + c2b

// ---------------- float <-> ordered-uint encoding for atomicMax ----------------
__device__ __forceinline__ unsigned fenc(float f) {
    unsigned u = __float_as_uint(f);
    return (u & 0x80000000u) ? ~u : (u | 0x80000000u);
}
__device__ __forceinline__ float fdec(unsigned u) {
    unsigned v = (u & 0x80000000u) ? (u & 0x7fffffffu) : ~u;
    return __uint_as_float(v);
}

// ---------------- weight-fusion precompute kernels ------------------------------
__global__ void fuse1_kernel(const float* __restrict__ c1w, const float* __restrict__ l1w,
                             const float* __restrict__ l1b, const float* __restrict__ c1b) {
    __shared__ float sl[64 * 64];
    int tid = threadIdx.x;
    for (int t = tid; t < 4096; t += 256) sl[t] = l1w[t];
    __syncthreads();
    for (int t = tid; t < 128 * 64; t += 256) {
        int o = t >> 6, i = t & 63;
        float s = 0.f;
#pragma unroll 8
        for (int j = 0; j < 64; j++) s = fmaf(c1w[o * 64 + j], sl[j * 64 + i], s);
        g_fw1[t] = s;
    }
    if (tid < 128) {
        float s = c1b[tid];
#pragma unroll 8
        for (int j = 0; j < 64; j++) s = fmaf(c1w[tid * 64 + j], l1b[j], s);
        g_fb1[tid] = s;
    }
}

// fw2[o][i] = sum_j c2w[o][j] * l2w[j][i]; 128 blocks x 8 rows
__global__ __launch_bounds__(256) void fuse2_kernel(const float* __restrict__ c2w,
                                                    const float* __restrict__ l2w) {
    extern __shared__ float sl[];                 // 128*128
    const int tid = threadIdx.x;
    for (int t = tid; t < 16384; t += 256) sl[t] = l2w[t];
    __syncthreads();
    const int i  = tid & 127;
    const int og = tid >> 7;                      // 0..1
    const int o0 = blockIdx.x * 8 + og * 4;
    float s0 = 0.f, s1 = 0.f, s2 = 0.f, s3 = 0.f;
    const float* w0 = c2w + (size_t)(o0 + 0) * 128;
    const float* w1 = c2w + (size_t)(o0 + 1) * 128;
    const float* w2 = c2w + (size_t)(o0 + 2) * 128;
    const float* w3 = c2w + (size_t)(o0 + 3) * 128;
#pragma unroll 4
    for (int j = 0; j < 128; j++) {
        float xv = sl[j * 128 + i];
        s0 = fmaf(w0[j], xv, s0);
        s1 = fmaf(w1[j], xv, s1);
        s2 = fmaf(w2[j], xv, s2);
        s3 = fmaf(w3[j], xv, s3);
    }
    g_fw2[(size_t)(o0 + 0) * 128 + i] = s0;
    g_fw2[(size_t)(o0 + 1) * 128 + i] = s1;
    g_fw2[(size_t)(o0 + 2) * 128 + i] = s2;
    g_fw2[(size_t)(o0 + 3) * 128 + i] = s3;
}

__global__ void fuse2b_kernel(const float* __restrict__ c2w, const float* __restrict__ l2b,
                              const float* __restrict__ c2b) {
    int o = blockIdx.x * 256 + threadIdx.x;
    if (o < 1024) {
        float s = c2b[o];
#pragma unroll 8
        for (int j = 0; j < 128; j++) s = fmaf(c2w[o * 128 + j], l2b[j], s);
        g_fb2[o] = s;
    }
}

// ---------------- KNN part 1 (R14 exact): packed-pair scan, partial top-16 -------
// Keys in acc space: d = dot(pn,pm) - 0.5*||pm||^2. Candidate PAIRS via
// fma.rn.f32x2. grid (128, 2): x = 256-query tile, y = 2048-candidate half.
__global__ __launch_bounds__(256) void knn_part_kernel(const float* __restrict__ pts) {
    const int b  = blockIdx.x >> 4;
    const int n  = ((blockIdx.x & 15) << 8) + threadIdx.x;
    const int m0 = blockIdx.y * 2048;
    const float* px = pts + b * 3 * NPTS;

    const float xn = px[n], yn = px[NPTS + n], zn = px[2 * NPTS + n];
    unsigned long long xn2, yn2, zn2;
    asm("mov.b64 %0, {%1, %1};" : "=l"(xn2) : "f"(xn));
    asm("mov.b64 %0, {%1, %1};" : "=l"(yn2) : "f"(yn));
    asm("mov.b64 %0, {%1, %1};" : "=l"(zn2) : "f"(zn));

    float kd[16]; int ki[16];
#pragma unroll
    for (int j = 0; j < 16; j++) { kd[j] = -FLT_MAX; ki[j] = 0; }

    __shared__ ulonglong2 tile_xy[1024];   // 16 KB: (x0,x1 | y0,y1)
    __shared__ ulonglong2 tile_zw[1024];   // 16 KB: (z0,z1 | w0,w1)

    for (int t = threadIdx.x; t < 1024; t += 256) {
        int m = m0 + 2 * t;
        float x0 = px[m],            x1 = px[m + 1];
        float y0 = px[NPTS + m],     y1 = px[NPTS + m + 1];
        float z0 = px[2 * NPTS + m], z1 = px[2 * NPTS + m + 1];
        float w0 = -0.5f * fmaf(x0, x0, fmaf(y0, y0, z0 * z0));
        float w1 = -0.5f * fmaf(x1, x1, fmaf(y1, y1, z1 * z1));
        *(float4*)&tile_xy[t] = make_float4(x0, x1, y0, y1);
        *(float4*)&tile_zw[t] = make_float4(z0, z1, w0, w1);
    }
    __syncthreads();

#pragma unroll 2
    for (int t = 0; t < 1024; t++) {
        ulonglong2 xy = tile_xy[t];   // .x = x01, .y = y01
        ulonglong2 zw = tile_zw[t];   // .x = z01, .y = w01
        unsigned long long d01;
        asm("fma.rn.f32x2 %0, %1, %2, %3;" : "=l"(d01) : "l"(xn2), "l"(xy.x), "l"(zw.y));
        asm("fma.rn.f32x2 %0, %1, %2, %3;" : "=l"(d01) : "l"(yn2), "l"(xy.y), "l"(d01));
        asm("fma.rn.f32x2 %0, %1, %2, %3;" : "=l"(d01) : "l"(zn2), "l"(zw.x), "l"(d01));
        float d0, d1;
        asm("mov.b64 {%0, %1}, %2;" : "=f"(d0), "=f"(d1) : "l"(d01));
        float wmax = fmaxf(d0, d1);
        if (wmax > kd[15]) {
            // slow path: insert d0 then d1 (ascending index -> stable ties)
#pragma unroll 1
            for (int h = 0; h < 2; h++) {
                float d = (h == 0) ? d0 : d1;
                if (d > kd[15]) {
                    const int ci = m0 + 2 * t + h;
                    bool done = false;
#pragma unroll
                    for (int j = 15; j > 0; --j) {
                        if (!done) {
                            if (kd[j - 1] < d) {
                                kd[j] = kd[j - 1]; ki[j] = ki[j - 1];
                                if (j == 1) { kd[0] = d; ki[0] = ci; }
                            } else {
                                kd[j] = d; ki[j] = ci;
                                done = true;
                            }
                        }
                    }
                }
            }
        }
    }
    const int p = b * NPTS + n;
    float* od = g_kd_part + ((size_t)p * 2 + blockIdx.y) * KNN_K;
    int*   oi = g_ki_part + ((size_t)p * 2 + blockIdx.y) * KNN_K;
#pragma unroll
    for (int j = 0; j < 16; j++) { od[j] = kd[j]; oi[j] = ki[j]; }
}

// ---------------- KNN part 2: merge the two sorted halves -----------------------
__global__ void knn_merge_kernel() {
    int p = blockIdx.x * 256 + threadIdx.x;
    if (p >= TOTAL_PTS) return;
    const float* dA = g_kd_part + (size_t)p * 2 * KNN_K;
    const int*   iA = g_ki_part + (size_t)p * 2 * KNN_K;
    const float* dB = dA + KNN_K;
    const int*   iB = iA + KNN_K;
    int* op = g_idx + (size_t)p * KNN_K;
    int a = 0, c = 0;
#pragma unroll
    for (int j = 0; j < 16; j++) {
        bool takeA = (c >= 16) || (a < 16 && dA[a] >= dB[c]);
        op[j] = takeA ? iA[a] : iB[c];
        if (takeA) a++; else c++;
    }
}

// ---------------- local covariance features: [p][12] --------------------------
__global__ void feat_kernel(const float* __restrict__ pts) {
    int p = blockIdx.x * 256 + threadIdx.x;
    if (p >= TOTAL_PTS) return;
    int b = p >> 12, n = p & (NPTS - 1);
    const float* px = pts + b * 3 * NPTS;
    int i0 = g_idx[p * KNN_K + 0];
    int i1 = g_idx[p * KNN_K + 1];
    float a0 = px[i0], a1 = px[NPTS + i0], a2 = px[2 * NPTS + i0];
    float c0 = px[i1], c1 = px[NPTS + i1], c2 = px[2 * NPTS + i1];
    float* f = g_feat + p * 12;
    f[0] = px[n]; f[1] = px[NPTS + n]; f[2] = px[2 * NPTS + n];
    f[3] = a0 * c0; f[4]  = a0 * c1; f[5]  = a0 * c2;
    f[6] = a1 * c0; f[7]  = a1 * c1; f[8]  = a1 * c2;
    f[9] = a2 * c0; f[10] = a2 * c1; f[11] = a2 * c2;
}

// ---------------- pointwise dense layer (oc-split, f32x2-packed accumulators) ----
// grid = (TOTAL_PTS/256, DOUT/DOUTB). Each thread: one point, DOUTB outputs.
template <int DIN, int DOUTB, int DOUT, bool RELU>
__global__ __launch_bounds__(256) void dense_kernel(
    const float* __restrict__ in, const float* __restrict__ W,
    const float* __restrict__ bias, float* __restrict__ out) {
    constexpr int SW = DOUTB + 4;
    extern __shared__ float sm[];
    float* sW  = sm;                            // DIN * SW   (sW[i][oc])
    float* sB  = sW + DIN * SW;                 // DOUTB
    float* sIn = sB + DOUTB;                    // 256 * (DIN+1)
    const int tid = threadIdx.x;
    const int oc0 = blockIdx.y * DOUTB;

    for (int t = tid; t < DIN * DOUTB; t += 256) {
        int oc = t / DIN, i = t - oc * DIN;
        sW[i * SW + oc] = W[(size_t)oc0 * DIN + t];
    }
    for (int t = tid; t < DOUTB; t += 256) sB[t] = bias[oc0 + t];
    const int p0 = blockIdx.x * 256;
    for (int t = tid; t < 256 * DIN; t += 256) {
        int r = t / DIN, c = t - r * DIN;
        sIn[r * (DIN + 1) + c] = in[(size_t)(p0 + r) * DIN + c];
    }
    __syncthreads();

    const float* myin = sIn + tid * (DIN + 1);
    float* op = out + (size_t)(p0 + tid) * DOUT + oc0;

#pragma unroll
    for (int c0 = 0; c0 < DOUTB; c0 += 16) {
        unsigned long long accp[8];     // 8 packed pairs = 16 oc accumulators
#pragma unroll
        for (int q = 0; q < 8; q++)
            asm("mov.b64 %0, {%1, %2};" : "=l"(accp[q])
                : "f"(sB[c0 + 2 * q]), "f"(sB[c0 + 2 * q + 1]));
#pragma unroll 4
        for (int i = 0; i < DIN; i++) {
            float xi = myin[i];
            unsigned long long xib;
            asm("mov.b64 %0, {%1, %1};" : "=l"(xib) : "f"(xi));
            const ulonglong2* wr = (const ulonglong2*)(sW + i * SW + c0);
#pragma unroll
            for (int q = 0; q < 4; q++) {
                ulonglong2 wp = wr[q];   // 2 packed weight pairs
                asm("fma.rn.f32x2 %0, %1, %2, %0;" : "+l"(accp[2 * q])     : "l"(xib), "l"(wp.x));
                asm("fma.rn.f32x2 %0, %1, %2, %0;" : "+l"(accp[2 * q + 1]) : "l"(xib), "l"(wp.y));
            }
        }
#pragma unroll
        for (int q = 0; q < 4; q++) {
            float4 v;
            asm("mov.b64 {%0, %1}, %2;" : "=f"(v.x), "=f"(v.y) : "l"(accp[2 * q]));
            asm("mov.b64 {%0, %1}, %2;" : "=f"(v.z), "=f"(v.w) : "l"(accp[2 * q + 1]));
            if (RELU) {
                v.x = fmaxf(v.x, 0.f); v.y = fmaxf(v.y, 0.f);
                v.z = fmaxf(v.z, 0.f); v.w = fmaxf(v.w, 0.f);
            }
            ((float4*)(op + c0))[q] = v;
        }
    }
}

// ---------------- neighbor max-pool over idx (float4 vectorized) -----------------
template <int D>
__global__ void maxpool_kernel(const float* __restrict__ in, float* __restrict__ out) {
    constexpr int DV = D / 4;
    int t = blockIdx.x * 256 + threadIdx.x;
    if (t >= TOTAL_PTS * DV) return;
    int p = t / DV;
    int c4 = t - p * DV;
    int base = (p >> 12) << 12;
    const int* id = g_idx + p * KNN_K;
    float4 m = make_float4(-FLT_MAX, -FLT_MAX, -FLT_MAX, -FLT_MAX);
#pragma unroll
    for (int k = 0; k < KNN_K; k++) {
        int j = id[k];
        float4 v = *(const float4*)(in + (size_t)(base + j) * D + c4 * 4);
        m.x = fmaxf(m.x, v.x); m.y = fmaxf(m.y, v.y);
        m.z = fmaxf(m.z, v.z); m.w = fmaxf(m.w, v.w);
    }
    ((float4*)out)[t] = m;
}

// ---------------- reset gmax -----------------------------------------------------
__global__ void reset_kernel() {
    int t = blockIdx.x * 256 + threadIdx.x;
    if (t < BATCH * 1024) g_gmax[t] = 0u;
}

// ---------------- fused l2+c2 (128->1024) GEMM + global max (f32x2-packed) -------
// 8 oc rows x 4 point-pairs per thread; x-pairs come pre-packed from ulonglong2
// shared loads (same conflict-free addresses); w broadcast via mov.b64.
__global__ __launch_bounds__(256) void c2max_kernel(const float* __restrict__ y) {
    extern __shared__ float sm[];
    float* sW = sm;                 // [i64][oc128] stride 132
    float* sX = sW + 64 * 132;      // [i64][p128]  stride 132
    float* sB = sX + 64 * 132;      // 128
    const int tid = threadIdx.x;
    const int pt0 = blockIdx.x * 128;
    const int oc0 = blockIdx.y * 128;
    const int b = pt0 >> 12;
    const int tx4 = (tid & 15) * 4, ty4 = (tid >> 4) * 4;

    if (tid < 128) sB[tid] = g_fb2[oc0 + tid];

    unsigned long long acc2[8][4];   // [oc row][pt pair], each = 2 packed fp32
#pragma unroll
    for (int j = 0; j < 8; j++)
#pragma unroll
        for (int q = 0; q < 4; q++) acc2[j][q] = 0ull;

    for (int kc = 0; kc < 128; kc += 64) {
        __syncthreads();
        for (int t = tid; t < 8192; t += 256) {
            int r = t >> 6, i = t & 63;
            sW[i * 132 + r] = g_fw2[(size_t)(oc0 + r) * 128 + kc + i];
            sX[i * 132 + r] = y[(size_t)(pt0 + r) * 128 + kc + i];
        }
        __syncthreads();

#pragma unroll 2
        for (int i = 0; i < 64; i++) {
            const float* wr = sW + i * 132;
            const float* xr = sX + i * 132;
            ulonglong2 xv0 = *(const ulonglong2*)(xr + tx4);        // (x0,x1)|(x2,x3)
            ulonglong2 xv1 = *(const ulonglong2*)(xr + 64 + tx4);   // (x4,x5)|(x6,x7)
            float4 w0 = *(const float4*)(wr + ty4);
            float4 w1 = *(const float4*)(wr + 64 + ty4);
            unsigned long long wb[8];
            asm("mov.b64 %0, {%1, %1};" : "=l"(wb[0]) : "f"(w0.x));
            asm("mov.b64 %0, {%1, %1};" : "=l"(wb[1]) : "f"(w0.y));
            asm("mov.b64 %0, {%1, %1};" : "=l"(wb[2]) : "f"(w0.z));
            asm("mov.b64 %0, {%1, %1};" : "=l"(wb[3]) : "f"(w0.w));
            asm("mov.b64 %0, {%1, %1};" : "=l"(wb[4]) : "f"(w1.x));
            asm("mov.b64 %0, {%1, %1};" : "=l"(wb[5]) : "f"(w1.y));
            asm("mov.b64 %0, {%1, %1};" : "=l"(wb[6]) : "f"(w1.z));
            asm("mov.b64 %0, {%1, %1};" : "=l"(wb[7]) : "f"(w1.w));
            unsigned long long xp[4] = {xv0.x, xv0.y, xv1.x, xv1.y};
#pragma unroll
            for (int j = 0; j < 8; j++)
#pragma unroll
                for (int q = 0; q < 4; q++)
                    asm("fma.rn.f32x2 %0, %1, %2, %0;"
                        : "+l"(acc2[j][q]) : "l"(wb[j]), "l"(xp[q]));
        }
    }

#pragma unroll
    for (int j = 0; j < 8; j++) {
        int ocl = (j < 4) ? (ty4 + j) : (64 + ty4 + j - 4);
        float m = -FLT_MAX;
#pragma unroll
        for (int q = 0; q < 4; q++) {
            float p0, p1;
            asm("mov.b64 {%0, %1}, %2;" : "=f"(p0), "=f"(p1) : "l"(acc2[j][q]));
            m = fmaxf(m, fmaxf(p0, p1));
        }
        m += sB[ocl];
#pragma unroll
        for (int off = 8; off >= 1; off >>= 1)
            m = fmaxf(m, __shfl_xor_sync(0xffffffffu, m, off));
        if ((tid & 15) == 0)
            atomicMax(&g_gmax[b * 1024 + oc0 + ocl], fenc(m));
    }
}

// ---------------- mlp2 -----------------------------------------------------------
// grid (BATCH, 4): each block computes 128 outputs, K split x2 per output pair.
__global__ __launch_bounds__(256) void mlp2a_kernel(const float* __restrict__ w,
                                                    const float* __restrict__ bias) {
    int b = blockIdx.x;
    __shared__ float sg[1024];
    for (int t = threadIdx.x; t < 1024; t += 256) sg[t] = fdec(g_gmax[b * 1024 + t]);
    __syncthreads();
    int o  = blockIdx.y * 128 + (threadIdx.x >> 1);
    int kh = (threadIdx.x & 1) * 512;
    const float* wr = w + (size_t)o * 1024 + kh;
    const float* xr = sg + kh;
    float acc = 0.f;
#pragma unroll 8
    for (int i = 0; i < 512; i++) acc = fmaf(wr[i], xr[i], acc);
    acc += __shfl_xor_sync(0xffffffffu, acc, 1);
    if ((threadIdx.x & 1) == 0)
        g_h[b * 512 + o] = fmaxf(acc + bias[o], 0.f);
}

__global__ void mlp2b_kernel(const float* __restrict__ w, const float* __restrict__ bias,
                             float* __restrict__ out) {
    int b = blockIdx.x;
    __shared__ float sh[512];
    if (threadIdx.x < 512) sh[threadIdx.x] = g_h[b * 512 + threadIdx.x];
    __syncthreads();
    int o = threadIdx.x;
    if (o < 512) {
        float acc = bias[o];
        const float* wr = w + (size_t)o * 512;
#pragma unroll 8
        for (int i = 0; i < 512; i++) acc = fmaf(wr[i], sh[i], acc);
        out[b * 512 + o] = acc;
    }
}

// ---------------- launch ---------------------------------------------------------
extern "C" void kernel_launch(void* const* d_in, const int* in_sizes, int n_in,
                              void* d_out, int out_size) {
    const float* pts  = (const float*)d_in[0];
    const float* m1w1 = (const float*)d_in[1];  const float* m1b1 = (const float*)d_in[2];
    const float* m1w2 = (const float*)d_in[3];  const float* m1b2 = (const float*)d_in[4];
    const float* m1w3 = (const float*)d_in[5];  const float* m1b3 = (const float*)d_in[6];
    const float* l1w  = (const float*)d_in[7];  const float* l1b  = (const float*)d_in[8];
    const float* c1w  = (const float*)d_in[9];  const float* c1b  = (const float*)d_in[10];
    const float* l2w  = (const float*)d_in[11]; const float* l2b  = (const float*)d_in[12];
    const float* c2w  = (const float*)d_in[13]; const float* c2b  = (const float*)d_in[14];
    const float* m2w1 = (const float*)d_in[15]; const float* m2b1 = (const float*)d_in[16];
    const float* m2w2 = (const float*)d_in[17]; const float* m2b2 = (const float*)d_in[18];
    float* out = (float*)d_out;

    float *bufA = nullptr, *bufB = nullptr, *feat = nullptr, *fw1 = nullptr, *fb1 = nullptr;
    cudaGetSymbolAddress((void**)&bufA, g_bufA);
    cudaGetSymbolAddress((void**)&bufB, g_bufB);
    cudaGetSymbolAddress((void**)&feat, g_feat);
    cudaGetSymbolAddress((void**)&fw1,  g_fw1);
    cudaGetSymbolAddress((void**)&fb1,  g_fb1);

    // dynamic smem sizes (floats * 4)
    const int smem_d12  = (12 * 36 + 32 + 256 * 13) * 4;    // ~15.2 KB
    const int smem_d64  = (64 * 36 + 32 + 256 * 65) * 4;    // ~75.9 KB
    const int smem_c2   = (2 * 64 * 132 + 128) * 4;         // ~68.1 KB
    const int smem_f2   = 128 * 128 * 4;                    // 64 KB

    cudaFuncSetAttribute(dense_kernel<64, 32, 64, true>,
                         cudaFuncAttributeMaxDynamicSharedMemorySize, smem_d64);
    cudaFuncSetAttribute(dense_kernel<64, 32, 128, true>,
                         cudaFuncAttributeMaxDynamicSharedMemorySize, smem_d64);
    cudaFuncSetAttribute(c2max_kernel,
                         cudaFuncAttributeMaxDynamicSharedMemorySize, smem_c2);
    cudaFuncSetAttribute(fuse2_kernel,
                         cudaFuncAttributeMaxDynamicSharedMemorySize, smem_f2);

    // 1. fused-weight precompute (independent of knn)
    fuse1_kernel<<<1, 256>>>(c1w, l1w, l1b, c1b);
    fuse2_kernel<<<128, 256, smem_f2>>>(c2w, l2w);
    fuse2b_kernel<<<4, 256>>>(c2w, l2b, c2b);
    // 2. KNN (R14 f32x2 packed-pair scan, split candidate halves) + merge + feats
    {
        dim3 g(128, 2);
        knn_part_kernel<<<g, 256>>>(pts);
    }
    knn_merge_kernel<<<128, 256>>>();
    feat_kernel<<<128, 256>>>(pts);
    // 3. mlp1
    {
        dim3 g(TOTAL_PTS / 256, 2);
        dense_kernel<12, 32, 64, true><<<g, 256, smem_d12>>>(feat, m1w1, m1b1, bufA);
        dense_kernel<64, 32, 64, true><<<g, 256, smem_d64>>>(bufA, m1w2, m1b2, bufB);
        dense_kernel<64, 32, 64, true><<<g, 256, smem_d64>>>(bufB, m1w3, m1b3, bufA);
    }
    // 4. graph layer (l1+c1 fused)
    maxpool_kernel<64><<<TOTAL_PTS * 16 / 256, 256>>>(bufA, bufB);
    {
        dim3 g(TOTAL_PTS / 256, 4);
        dense_kernel<64, 32, 128, true><<<g, 256, smem_d64>>>(bufB, fw1, fb1, bufA);
    }
    maxpool_kernel<128><<<TOTAL_PTS * 32 / 256, 256>>>(bufA, bufB);
    // 5. fused l2+c2 + global max
    reset_kernel<<<32, 256>>>();
    {
        dim3 grid(TOTAL_PTS / 128, 8);
        c2max_kernel<<<grid, 256, smem_c2>>>(bufB);
    }
    // 6. mlp2
    {
        dim3 g(BATCH, 4);
        mlp2a_kernel<<<g, 256>>>(m2w1, m2b1);
    }
    mlp2b_kernel<<<BATCH, 512>>>(m2w2, m2b2, out);
}

// round 17
// speedup vs baseline: 1.1890x; 1.0748x over previous
#include <cuda_runtime.h>
#include <cuda_bf16.h>
#include <float.h>
#include <math.h>

// Problem constants
#define BATCH 8
#define NPTS  4096
#define KNN_K 16
#define TOTAL_PTS (BATCH * NPTS)   // 32768

// ---------------- scratch (static device memory; no allocation) ----------------
__device__ float    g_bufA[TOTAL_PTS * 128];   // 16 MB
__device__ float    g_bufB[TOTAL_PTS * 128];   // 16 MB
__device__ float    g_feat[TOTAL_PTS * 12];
__device__ int      g_idx[TOTAL_PTS * KNN_K];
__device__ unsigned g_gmax[BATCH * 1024];
__device__ float    g_h[BATCH * 512];
// fused weights
__device__ float    g_fw1[128 * 64];           // c1w @ l1w
__device__ float    g_fb1[128];                // c1w @ l1b + c1b
__device__ float    g_fw2[1024 * 128];         // c2w @ l2w
__device__ float    g_fb2[1024];               // c2w @ l2b + c2b

// ---------------- float <-> ordered-uint encoding for atomicMax ----------------
__device__ __forceinline__ unsigned fenc(float f) {
    unsigned u = __float_as_uint(f);
    return (u & 0x80000000u) ? ~u : (u | 0x80000000u);
}
__device__ __forceinline__ float fdec(unsigned u) {
    unsigned v = (u & 0x80000000u) ? (u & 0x7fffffffu) : ~u;
    return __uint_as_float(v);
}

// ---------------- weight-fusion precompute kernels ------------------------------
__global__ void fuse1_kernel(const float* __restrict__ c1w, const float* __restrict__ l1w,
                             const float* __restrict__ l1b, const float* __restrict__ c1b) {
    __shared__ float sl[64 * 64];
    int tid = threadIdx.x;
    for (int t = tid; t < 4096; t += 256) sl[t] = l1w[t];
    __syncthreads();
    for (int t = tid; t < 128 * 64; t += 256) {
        int o = t >> 6, i = t & 63;
        float s = 0.f;
#pragma unroll 8
        for (int j = 0; j < 64; j++) s = fmaf(c1w[o * 64 + j], sl[j * 64 + i], s);
        g_fw1[t] = s;
    }
    if (tid < 128) {
        float s = c1b[tid];
#pragma unroll 8
        for (int j = 0; j < 64; j++) s = fmaf(c1w[tid * 64 + j], l1b[j], s);
        g_fb1[tid] = s;
    }
}

// fw2[o][i] = sum_j c2w[o][j] * l2w[j][i]; 128 blocks x 8 rows
__global__ __launch_bounds__(256) void fuse2_kernel(const float* __restrict__ c2w,
                                                    const float* __restrict__ l2w) {
    extern __shared__ float sl[];                 // 128*128
    const int tid = threadIdx.x;
    for (int t = tid; t < 16384; t += 256) sl[t] = l2w[t];
    __syncthreads();
    const int i  = tid & 127;
    const int og = tid >> 7;                      // 0..1
    const int o0 = blockIdx.x * 8 + og * 4;
    float s0 = 0.f, s1 = 0.f, s2 = 0.f, s3 = 0.f;
    const float* w0 = c2w + (size_t)(o0 + 0) * 128;
    const float* w1 = c2w + (size_t)(o0 + 1) * 128;
    const float* w2 = c2w + (size_t)(o0 + 2) * 128;
    const float* w3 = c2w + (size_t)(o0 + 3) * 128;
#pragma unroll 4
    for (int j = 0; j < 128; j++) {
        float xv = sl[j * 128 + i];
        s0 = fmaf(w0[j], xv, s0);
        s1 = fmaf(w1[j], xv, s1);
        s2 = fmaf(w2[j], xv, s2);
        s3 = fmaf(w3[j], xv, s3);
    }
    g_fw2[(size_t)(o0 + 0) * 128 + i] = s0;
    g_fw2[(size_t)(o0 + 1) * 128 + i] = s1;
    g_fw2[(size_t)(o0 + 2) * 128 + i] = s2;
    g_fw2[(size_t)(o0 + 3) * 128 + i] = s3;
}

__global__ void fuse2b_kernel(const float* __restrict__ c2w, const float* __restrict__ l2b,
                              const float* __restrict__ c2b) {
    int o = blockIdx.x * 256 + threadIdx.x;
    if (o < 1024) {
        float s = c2b[o];
#pragma unroll 8
        for (int j = 0; j < 128; j++) s = fmaf(c2w[o * 128 + j], l2b[j], s);
        g_fb2[o] = s;
    }
}

// ---------------- KNN: single-scan (S=1) packed-pair top-16 ----------------------
// One top-16 list per query (single warm-up); loops over two 32 KB pair-tiles.
// Keys in acc space: d = dot(pn,pm) - 0.5*||pm||^2 (ordering == -0.5*dist^2 +
// const per query). Candidate PAIRS via fma.rn.f32x2.
__global__ __launch_bounds__(256) void knn_kernel(const float* __restrict__ pts) {
    const int b = blockIdx.x >> 4;               // 16 blocks per batch
    const int n = ((blockIdx.x & 15) << 8) + threadIdx.x;
    const float* px = pts + b * 3 * NPTS;

    const float xn = px[n], yn = px[NPTS + n], zn = px[2 * NPTS + n];
    unsigned long long xn2, yn2, zn2;
    asm("mov.b64 %0, {%1, %1};" : "=l"(xn2) : "f"(xn));
    asm("mov.b64 %0, {%1, %1};" : "=l"(yn2) : "f"(yn));
    asm("mov.b64 %0, {%1, %1};" : "=l"(zn2) : "f"(zn));

    float kd[16]; int ki[16];
#pragma unroll
    for (int j = 0; j < 16; j++) { kd[j] = -FLT_MAX; ki[j] = 0; }

    __shared__ ulonglong2 tile_xy[1024];   // 16 KB: (x0,x1 | y0,y1)
    __shared__ ulonglong2 tile_zw[1024];   // 16 KB: (z0,z1 | w0,w1), w=-0.5*||p||^2

    for (int m0 = 0; m0 < NPTS; m0 += 2048) {
        __syncthreads();
        for (int t = threadIdx.x; t < 1024; t += 256) {
            int m = m0 + 2 * t;
            float x0 = px[m],            x1 = px[m + 1];
            float y0 = px[NPTS + m],     y1 = px[NPTS + m + 1];
            float z0 = px[2 * NPTS + m], z1 = px[2 * NPTS + m + 1];
            float w0 = -0.5f * fmaf(x0, x0, fmaf(y0, y0, z0 * z0));
            float w1 = -0.5f * fmaf(x1, x1, fmaf(y1, y1, z1 * z1));
            *(float4*)&tile_xy[t] = make_float4(x0, x1, y0, y1);
            *(float4*)&tile_zw[t] = make_float4(z0, z1, w0, w1);
        }
        __syncthreads();

#pragma unroll 2
        for (int t = 0; t < 1024; t++) {
            ulonglong2 xy = tile_xy[t];   // .x = x01, .y = y01
            ulonglong2 zw = tile_zw[t];   // .x = z01, .y = w01
            unsigned long long d01;
            asm("fma.rn.f32x2 %0, %1, %2, %3;" : "=l"(d01) : "l"(xn2), "l"(xy.x), "l"(zw.y));
            asm("fma.rn.f32x2 %0, %1, %2, %3;" : "=l"(d01) : "l"(yn2), "l"(xy.y), "l"(d01));
            asm("fma.rn.f32x2 %0, %1, %2, %3;" : "=l"(d01) : "l"(zn2), "l"(zw.x), "l"(d01));
            float d0, d1;
            asm("mov.b64 {%0, %1}, %2;" : "=f"(d0), "=f"(d1) : "l"(d01));
            if (fmaxf(d0, d1) > kd[15]) {
                // slow path: insert d0 then d1 (ascending index -> stable ties)
#pragma unroll 1
                for (int h = 0; h < 2; h++) {
                    float d = (h == 0) ? d0 : d1;
                    if (d > kd[15]) {
                        const int ci = m0 + 2 * t + h;
                        bool done = false;
#pragma unroll
                        for (int j = 15; j > 0; --j) {
                            if (!done) {
                                if (kd[j - 1] < d) {
                                    kd[j] = kd[j - 1]; ki[j] = ki[j - 1];
                                    if (j == 1) { kd[0] = d; ki[0] = ci; }
                                } else {
                                    kd[j] = d; ki[j] = ci;
                                    done = true;
                                }
                            }
                        }
                    }
                }
            }
        }
    }
    int* op = g_idx + (size_t)(b * NPTS + n) * KNN_K;
#pragma unroll
    for (int j = 0; j < 16; j++) op[j] = ki[j];
}

// ---------------- local covariance features: [p][12] --------------------------
__global__ void feat_kernel(const float* __restrict__ pts) {
    int p = blockIdx.x * 256 + threadIdx.x;
    if (p >= TOTAL_PTS) return;
    int b = p >> 12, n = p & (NPTS - 1);
    const float* px = pts + b * 3 * NPTS;
    int i0 = g_idx[p * KNN_K + 0];
    int i1 = g_idx[p * KNN_K + 1];
    float a0 = px[i0], a1 = px[NPTS + i0], a2 = px[2 * NPTS + i0];
    float c0 = px[i1], c1 = px[NPTS + i1], c2 = px[2 * NPTS + i1];
    float* f = g_feat + p * 12;
    f[0] = px[n]; f[1] = px[NPTS + n]; f[2] = px[2 * NPTS + n];
    f[3] = a0 * c0; f[4]  = a0 * c1; f[5]  = a0 * c2;
    f[6] = a1 * c0; f[7]  = a1 * c1; f[8]  = a1 * c2;
    f[9] = a2 * c0; f[10] = a2 * c1; f[11] = a2 * c2;
}

// ---------------- pointwise dense layer (oc-split, f32x2-packed accumulators) ----
template <int DIN, int DOUTB, int DOUT, bool RELU>
__global__ __launch_bounds__(256) void dense_kernel(
    const float* __restrict__ in, const float* __restrict__ W,
    const float* __restrict__ bias, float* __restrict__ out) {
    constexpr int SW = DOUTB + 4;
    extern __shared__ float sm[];
    float* sW  = sm;                            // DIN * SW   (sW[i][oc])
    float* sB  = sW + DIN * SW;                 // DOUTB
    float* sIn = sB + DOUTB;                    // 256 * (DIN+1)
    const int tid = threadIdx.x;
    const int oc0 = blockIdx.y * DOUTB;

    for (int t = tid; t < DIN * DOUTB; t += 256) {
        int oc = t / DIN, i = t - oc * DIN;
        sW[i * SW + oc] = W[(size_t)oc0 * DIN + t];
    }
    for (int t = tid; t < DOUTB; t += 256) sB[t] = bias[oc0 + t];
    const int p0 = blockIdx.x * 256;
    for (int t = tid; t < 256 * DIN; t += 256) {
        int r = t / DIN, c = t - r * DIN;
        sIn[r * (DIN + 1) + c] = in[(size_t)(p0 + r) * DIN + c];
    }
    __syncthreads();

    const float* myin = sIn + tid * (DIN + 1);
    float* op = out + (size_t)(p0 + tid) * DOUT + oc0;

#pragma unroll
    for (int c0 = 0; c0 < DOUTB; c0 += 16) {
        unsigned long long accp[8];     // 8 packed pairs = 16 oc accumulators
#pragma unroll
        for (int q = 0; q < 8; q++)
            asm("mov.b64 %0, {%1, %2};" : "=l"(accp[q])
                : "f"(sB[c0 + 2 * q]), "f"(sB[c0 + 2 * q + 1]));
#pragma unroll 4
        for (int i = 0; i < DIN; i++) {
            float xi = myin[i];
            unsigned long long xib;
            asm("mov.b64 %0, {%1, %1};" : "=l"(xib) : "f"(xi));
            const ulonglong2* wr = (const ulonglong2*)(sW + i * SW + c0);
#pragma unroll
            for (int q = 0; q < 4; q++) {
                ulonglong2 wp = wr[q];   // 2 packed weight pairs
                asm("fma.rn.f32x2 %0, %1, %2, %0;" : "+l"(accp[2 * q])     : "l"(xib), "l"(wp.x));
                asm("fma.rn.f32x2 %0, %1, %2, %0;" : "+l"(accp[2 * q + 1]) : "l"(xib), "l"(wp.y));
            }
        }
#pragma unroll
        for (int q = 0; q < 4; q++) {
            float4 v;
            asm("mov.b64 {%0, %1}, %2;" : "=f"(v.x), "=f"(v.y) : "l"(accp[2 * q]));
            asm("mov.b64 {%0, %1}, %2;" : "=f"(v.z), "=f"(v.w) : "l"(accp[2 * q + 1]));
            if (RELU) {
                v.x = fmaxf(v.x, 0.f); v.y = fmaxf(v.y, 0.f);
                v.z = fmaxf(v.z, 0.f); v.w = fmaxf(v.w, 0.f);
            }
            ((float4*)(op + c0))[q] = v;
        }
    }
}

// ---------------- neighbor max-pool over idx (float4 vectorized) -----------------
template <int D>
__global__ void maxpool_kernel(const float* __restrict__ in, float* __restrict__ out) {
    constexpr int DV = D / 4;
    int t = blockIdx.x * 256 + threadIdx.x;
    if (t >= TOTAL_PTS * DV) return;
    int p = t / DV;
    int c4 = t - p * DV;
    int base = (p >> 12) << 12;
    const int* id = g_idx + p * KNN_K;
    float4 m = make_float4(-FLT_MAX, -FLT_MAX, -FLT_MAX, -FLT_MAX);
#pragma unroll
    for (int k = 0; k < KNN_K; k++) {
        int j = id[k];
        float4 v = *(const float4*)(in + (size_t)(base + j) * D + c4 * 4);
        m.x = fmaxf(m.x, v.x); m.y = fmaxf(m.y, v.y);
        m.z = fmaxf(m.z, v.z); m.w = fmaxf(m.w, v.w);
    }
    ((float4*)out)[t] = m;
}

// ---------------- reset gmax -----------------------------------------------------
__global__ void reset_kernel() {
    int t = blockIdx.x * 256 + threadIdx.x;
    if (t < BATCH * 1024) g_gmax[t] = 0u;
}

// ---------------- fused l2+c2 (128->1024) GEMM + global max (f32x2-packed) -------
__global__ __launch_bounds__(256) void c2max_kernel(const float* __restrict__ y) {
    extern __shared__ float sm[];
    float* sW = sm;                 // [i64][oc128] stride 132
    float* sX = sW + 64 * 132;      // [i64][p128]  stride 132
    float* sB = sX + 64 * 132;      // 128
    const int tid = threadIdx.x;
    const int pt0 = blockIdx.x * 128;
    const int oc0 = blockIdx.y * 128;
    const int b = pt0 >> 12;
    const int tx4 = (tid & 15) * 4, ty4 = (tid >> 4) * 4;

    if (tid < 128) sB[tid] = g_fb2[oc0 + tid];

    unsigned long long acc2[8][4];   // [oc row][pt pair], each = 2 packed fp32
#pragma unroll
    for (int j = 0; j < 8; j++)
#pragma unroll
        for (int q = 0; q < 4; q++) acc2[j][q] = 0ull;

    for (int kc = 0; kc < 128; kc += 64) {
        __syncthreads();
        for (int t = tid; t < 8192; t += 256) {
            int r = t >> 6, i = t & 63;
            sW[i * 132 + r] = g_fw2[(size_t)(oc0 + r) * 128 + kc + i];
            sX[i * 132 + r] = y[(size_t)(pt0 + r) * 128 + kc + i];
        }
        __syncthreads();

#pragma unroll 2
        for (int i = 0; i < 64; i++) {
            const float* wr = sW + i * 132;
            const float* xr = sX + i * 132;
            ulonglong2 xv0 = *(const ulonglong2*)(xr + tx4);
            ulonglong2 xv1 = *(const ulonglong2*)(xr + 64 + tx4);
            float4 w0 = *(const float4*)(wr + ty4);
            float4 w1 = *(const float4*)(wr + 64 + ty4);
            unsigned long long wb[8];
            asm("mov.b64 %0, {%1, %1};" : "=l"(wb[0]) : "f"(w0.x));
            asm("mov.b64 %0, {%1, %1};" : "=l"(wb[1]) : "f"(w0.y));
            asm("mov.b64 %0, {%1, %1};" : "=l"(wb[2]) : "f"(w0.z));
            asm("mov.b64 %0, {%1, %1};" : "=l"(wb[3]) : "f"(w0.w));
            asm("mov.b64 %0, {%1, %1};" : "=l"(wb[4]) : "f"(w1.x));
            asm("mov.b64 %0, {%1, %1};" : "=l"(wb[5]) : "f"(w1.y));
            asm("mov.b64 %0, {%1, %1};" : "=l"(wb[6]) : "f"(w1.z));
            asm("mov.b64 %0, {%1, %1};" : "=l"(wb[7]) : "f"(w1.w));
            unsigned long long xp[4] = {xv0.x, xv0.y, xv1.x, xv1.y};
#pragma unroll
            for (int j = 0; j < 8; j++)
#pragma unroll
                for (int q = 0; q < 4; q++)
                    asm("fma.rn.f32x2 %0, %1, %2, %0;"
                        : "+l"(acc2[j][q]) : "l"(wb[j]), "l"(xp[q]));
        }
    }

#pragma unroll
    for (int j = 0; j < 8; j++) {
        int ocl = (j < 4) ? (ty4 + j) : (64 + ty4 + j - 4);
        float m = -FLT_MAX;
#pragma unroll
        for (int q = 0; q < 4; q++) {
            float p0, p1;
            asm("mov.b64 {%0, %1}, %2;" : "=f"(p0), "=f"(p1) : "l"(acc2[j][q]));
            m = fmaxf(m, fmaxf(p0, p1));
        }
        m += sB[ocl];
#pragma unroll
        for (int off = 8; off >= 1; off >>= 1)
            m = fmaxf(m, __shfl_xor_sync(0xffffffffu, m, off));
        if ((tid & 15) == 0)
            atomicMax(&g_gmax[b * 1024 + oc0 + ocl], fenc(m));
    }
}

// ---------------- mlp2 -----------------------------------------------------------
__global__ __launch_bounds__(256) void mlp2a_kernel(const float* __restrict__ w,
                                                    const float* __restrict__ bias) {
    int b = blockIdx.x;
    __shared__ float sg[1024];
    for (int t = threadIdx.x; t < 1024; t += 256) sg[t] = fdec(g_gmax[b * 1024 + t]);
    __syncthreads();
    int o  = blockIdx.y * 128 + (threadIdx.x >> 1);
    int kh = (threadIdx.x & 1) * 512;
    const float* wr = w + (size_t)o * 1024 + kh;
    const float* xr = sg + kh;
    float acc = 0.f;
#pragma unroll 8
    for (int i = 0; i < 512; i++) acc = fmaf(wr[i], xr[i], acc);
    acc += __shfl_xor_sync(0xffffffffu, acc, 1);
    if ((threadIdx.x & 1) == 0)
        g_h[b * 512 + o] = fmaxf(acc + bias[o], 0.f);
}

__global__ void mlp2b_kernel(const float* __restrict__ w, const float* __restrict__ bias,
                             float* __restrict__ out) {
    int b = blockIdx.x;
    __shared__ float sh[512];
    if (threadIdx.x < 512) sh[threadIdx.x] = g_h[b * 512 + threadIdx.x];
    __syncthreads();
    int o = threadIdx.x;
    if (o < 512) {
        float acc = bias[o];
        const float* wr = w + (size_t)o * 512;
#pragma unroll 8
        for (int i = 0; i < 512; i++) acc = fmaf(wr[i], sh[i], acc);
        out[b * 512 + o] = acc;
    }
}

// ---------------- launch ---------------------------------------------------------
extern "C" void kernel_launch(void* const* d_in, const int* in_sizes, int n_in,
                              void* d_out, int out_size) {
    const float* pts  = (const float*)d_in[0];
    const float* m1w1 = (const float*)d_in[1];  const float* m1b1 = (const float*)d_in[2];
    const float* m1w2 = (const float*)d_in[3];  const float* m1b2 = (const float*)d_in[4];
    const float* m1w3 = (const float*)d_in[5];  const float* m1b3 = (const float*)d_in[6];
    const float* l1w  = (const float*)d_in[7];  const float* l1b  = (const float*)d_in[8];
    const float* c1w  = (const float*)d_in[9];  const float* c1b  = (const float*)d_in[10];
    const float* l2w  = (const float*)d_in[11]; const float* l2b  = (const float*)d_in[12];
    const float* c2w  = (const float*)d_in[13]; const float* c2b  = (const float*)d_in[14];
    const float* m2w1 = (const float*)d_in[15]; const float* m2b1 = (const float*)d_in[16];
    const float* m2w2 = (const float*)d_in[17]; const float* m2b2 = (const float*)d_in[18];
    float* out = (float*)d_out;

    float *bufA = nullptr, *bufB = nullptr, *feat = nullptr, *fw1 = nullptr, *fb1 = nullptr;
    cudaGetSymbolAddress((void**)&bufA, g_bufA);
    cudaGetSymbolAddress((void**)&bufB, g_bufB);
    cudaGetSymbolAddress((void**)&feat, g_feat);
    cudaGetSymbolAddress((void**)&fw1,  g_fw1);
    cudaGetSymbolAddress((void**)&fb1,  g_fb1);

    // dynamic smem sizes (floats * 4)
    const int smem_d12  = (12 * 36 + 32 + 256 * 13) * 4;    // ~15.2 KB
    const int smem_d64  = (64 * 36 + 32 + 256 * 65) * 4;    // ~75.9 KB
    const int smem_c2   = (2 * 64 * 132 + 128) * 4;         // ~68.1 KB
    const int smem_f2   = 128 * 128 * 4;                    // 64 KB

    cudaFuncSetAttribute(dense_kernel<64, 32, 64, true>,
                         cudaFuncAttributeMaxDynamicSharedMemorySize, smem_d64);
    cudaFuncSetAttribute(dense_kernel<64, 32, 128, true>,
                         cudaFuncAttributeMaxDynamicSharedMemorySize, smem_d64);
    cudaFuncSetAttribute(c2max_kernel,
                         cudaFuncAttributeMaxDynamicSharedMemorySize, smem_c2);
    cudaFuncSetAttribute(fuse2_kernel,
                         cudaFuncAttributeMaxDynamicSharedMemorySize, smem_f2);

    // 1. KNN (single-scan packed) + features
    knn_kernel<<<128, 256>>>(pts);
    feat_kernel<<<128, 256>>>(pts);
    // 2. mlp1  (launch #4 = dense<64,64> -> profiled by ncu next round)
    {
        dim3 g(TOTAL_PTS / 256, 2);
        dense_kernel<12, 32, 64, true><<<g, 256, smem_d12>>>(feat, m1w1, m1b1, bufA);
        dense_kernel<64, 32, 64, true><<<g, 256, smem_d64>>>(bufA, m1w2, m1b2, bufB);
        dense_kernel<64, 32, 64, true><<<g, 256, smem_d64>>>(bufB, m1w3, m1b3, bufA);
    }
    // 3. fused-weight precompute (needed before l1c1 / c2max)
    fuse1_kernel<<<1, 256>>>(c1w, l1w, l1b, c1b);
    fuse2_kernel<<<128, 256, smem_f2>>>(c2w, l2w);
    fuse2b_kernel<<<4, 256>>>(c2w, l2b, c2b);
    // 4. graph layer (l1+c1 fused)
    maxpool_kernel<64><<<TOTAL_PTS * 16 / 256, 256>>>(bufA, bufB);
    {
        dim3 g(TOTAL_PTS / 256, 4);
        dense_kernel<64, 32, 128, true><<<g, 256, smem_d64>>>(bufB, fw1, fb1, bufA);
    }
    maxpool_kernel<128><<<TOTAL_PTS * 32 / 256, 256>>>(bufA, bufB);
    // 5. fused l2+c2 + global max
    reset_kernel<<<32, 256>>>();
    {
        dim3 grid(TOTAL_PTS / 128, 8);
        c2max_kernel<<<grid, 256, smem_c2>>>(bufB);
    }
    // 6. mlp2
    {
        dim3 g(BATCH, 4);
        mlp2a_kernel<<<g, 256>>>(m2w1, m2b1);
    }
    mlp2b_kernel<<<BATCH, 512>>>(m2w2, m2b2, out);
}